// round 1
// baseline (speedup 1.0000x reference)
#include <cuda_runtime.h>
#include <cuda_bf16.h>

#define NMAX 100000

// Scratch (static device globals — allocation-free per harness rules)
__device__ __align__(16) float g_ylr[NMAX * 128];  // projected [y_l | y_r], node-major
__device__ __align__(16) float g_agg[NMAX * 64];   // aggregation accumulator
__device__ __align__(16) float g_x[NMAX * 64];     // layer activations
__device__ __align__(16) float g_inv[NMAX];        // 1/max(deg,1)
__device__ __align__(16) float g_deg[NMAX];        // in-degree (float count)

// ---------------------------------------------------------------------------
// zero
// ---------------------------------------------------------------------------
__global__ void zero_kernel(float* __restrict__ p, int count) {
    int i = blockIdx.x * blockDim.x + threadIdx.x;
    int n4 = count >> 2;
    float4* p4 = reinterpret_cast<float4*>(p);
    float4 z = make_float4(0.f, 0.f, 0.f, 0.f);
    for (int j = i; j < n4; j += gridDim.x * blockDim.x) p4[j] = z;
    if (i == 0) {
        for (int j = n4 * 4; j < count; ++j) p[j] = 0.f;
    }
}

// ---------------------------------------------------------------------------
// degree
// ---------------------------------------------------------------------------
__global__ void deg_kernel(const int* __restrict__ dst, float* __restrict__ deg, int E) {
    int i = blockIdx.x * blockDim.x + threadIdx.x;
    if (i < E) atomicAdd(&deg[dst[i]], 1.0f);
}

__global__ void inv_kernel(const float* __restrict__ deg, float* __restrict__ inv, int n) {
    int i = blockIdx.x * blockDim.x + threadIdx.x;
    if (i < n) inv[i] = 1.0f / fmaxf(deg[i], 1.0f);
}

// ---------------------------------------------------------------------------
// projection: ylr[node][0:F)   = x @ w_l   (no bias; bias applied in combine)
//             ylr[node][F:2F)  = x @ w_r
// Register-tiled smem GEMM. Threads = (NC/TN) * (BM/TM) must equal blockDim.
// ---------------------------------------------------------------------------
template <int K, int NC, int BM, int TM, int TN>
__global__ void proj_kernel(const float* __restrict__ x, const float* __restrict__ wl,
                            const float* __restrict__ wr, float* __restrict__ ylr, int n) {
    constexpr int PAD = 4;
    constexpr int F = NC / 2;
    constexpr int KV = K / 4;
    extern __shared__ float sm[];
    float* sW = sm;               // K * NC
    float* sX = sm + K * NC;      // BM * (K + PAD)

    const int tid = threadIdx.x;
    const int nb = blockIdx.x * BM;

    for (int idx = tid; idx < K * NC; idx += blockDim.x) {
        int k = idx / NC, j = idx % NC;
        sW[idx] = (j < F) ? wl[k * F + j] : wr[k * F + (j - F)];
    }
    for (int idx = tid; idx < BM * KV; idx += blockDim.x) {
        int m = idx / KV, kc = idx % KV;
        float4 v = make_float4(0.f, 0.f, 0.f, 0.f);
        if (nb + m < n) v = reinterpret_cast<const float4*>(x)[(size_t)(nb + m) * KV + kc];
        float* d = &sX[m * (K + PAD) + kc * 4];
        d[0] = v.x; d[1] = v.y; d[2] = v.z; d[3] = v.w;
    }
    __syncthreads();

    constexpr int CG = NC / TN;
    const int tj = tid % CG;
    const int ti = tid / CG;
    const int m0 = ti * TM;
    const int j0 = tj * TN;

    float acc[TM][TN];
#pragma unroll
    for (int i = 0; i < TM; ++i)
#pragma unroll
        for (int t = 0; t < TN; ++t) acc[i][t] = 0.f;

#pragma unroll 4
    for (int k = 0; k < K; ++k) {
        float bv[TN];
#pragma unroll
        for (int t = 0; t < TN; ++t) bv[t] = sW[k * NC + j0 + t];
#pragma unroll
        for (int i = 0; i < TM; ++i) {
            float a = sX[(m0 + i) * (K + PAD) + k];
#pragma unroll
            for (int t = 0; t < TN; ++t) acc[i][t] = fmaf(a, bv[t], acc[i][t]);
        }
    }

#pragma unroll
    for (int i = 0; i < TM; ++i) {
        int node = nb + m0 + i;
        if (node < n) {
#pragma unroll
            for (int t = 0; t < TN; ++t) ylr[(size_t)node * NC + j0 + t] = acc[i][t];
        }
    }
}

// ---------------------------------------------------------------------------
// layer 3 projection (Fin=16, Fout=9): simple per-node kernel, stride 18
// ---------------------------------------------------------------------------
__global__ void proj3_kernel(const float* __restrict__ x, const float* __restrict__ wl,
                             const float* __restrict__ wr, float* __restrict__ ylr, int n) {
    __shared__ float swl[16 * 9];
    __shared__ float swr[16 * 9];
    for (int i = threadIdx.x; i < 144; i += blockDim.x) {
        swl[i] = wl[i];
        swr[i] = wr[i];
    }
    __syncthreads();

    int node = blockIdx.x * blockDim.x + threadIdx.x;
    if (node >= n) return;

    float xv[16];
    const float4* xr = reinterpret_cast<const float4*>(x + (size_t)node * 16);
#pragma unroll
    for (int c = 0; c < 4; ++c) {
        float4 v = xr[c];
        xv[c * 4 + 0] = v.x; xv[c * 4 + 1] = v.y; xv[c * 4 + 2] = v.z; xv[c * 4 + 3] = v.w;
    }
#pragma unroll
    for (int j = 0; j < 9; ++j) {
        float al = 0.f, ar = 0.f;
#pragma unroll
        for (int k = 0; k < 16; ++k) {
            al = fmaf(xv[k], swl[k * 9 + j], al);
            ar = fmaf(xv[k], swr[k * 9 + j], ar);
        }
        ylr[(size_t)node * 18 + j] = al;
        ylr[(size_t)node * 18 + 9 + j] = ar;
    }
}

// ---------------------------------------------------------------------------
// scatter: agg[dst] += y_l[src]   (vec4 reduction, F % 4 == 0)
// ---------------------------------------------------------------------------
template <int F>
__global__ void scatter_kernel(const float* __restrict__ ylr, const int* __restrict__ src,
                               const int* __restrict__ dst, float* __restrict__ agg, int E) {
    constexpr int CH = F / 4;
    int idx = blockIdx.x * blockDim.x + threadIdx.x;
    if (idx >= E * CH) return;
    int e = idx / CH, c = idx % CH;
    int s = __ldg(src + e), d = __ldg(dst + e);
    float4 v = reinterpret_cast<const float4*>(ylr)[(size_t)s * (2 * F / 4) + c];
    float* addr = agg + (size_t)d * F + c * 4;
    asm volatile("red.global.add.v4.f32 [%0], {%1, %2, %3, %4};"
                 :: "l"(addr), "f"(v.x), "f"(v.y), "f"(v.z), "f"(v.w)
                 : "memory");
}

// scatter for F=9 (scalar atomics)
__global__ void scatter9_kernel(const float* __restrict__ ylr, const int* __restrict__ src,
                                const int* __restrict__ dst, float* __restrict__ agg, int E) {
    int idx = blockIdx.x * blockDim.x + threadIdx.x;
    if (idx >= E * 9) return;
    int e = idx / 9, c = idx % 9;
    int s = __ldg(src + e), d = __ldg(dst + e);
    atomicAdd(agg + (size_t)d * 9 + c, ylr[(size_t)s * 18 + c]);
}

// ---------------------------------------------------------------------------
// combine: out = [relu]( agg/deg + y_r + b )
// ---------------------------------------------------------------------------
template <int F, bool RELU>
__global__ void combine_kernel(const float* __restrict__ agg, const float* __restrict__ ylr,
                               const float* __restrict__ bias, const float* __restrict__ inv,
                               float* __restrict__ out, int n) {
    constexpr int CH = F / 4;
    int idx = blockIdx.x * blockDim.x + threadIdx.x;
    if (idx >= n * CH) return;
    int node = idx / CH, c = idx % CH;
    float iv = __ldg(inv + node);
    float4 a = reinterpret_cast<const float4*>(agg)[(size_t)node * CH + c];
    float4 r = reinterpret_cast<const float4*>(ylr)[(size_t)node * (2 * CH) + CH + c];
    float4 b = reinterpret_cast<const float4*>(bias)[c];
    float4 v;
    v.x = fmaf(a.x, iv, r.x) + b.x;
    v.y = fmaf(a.y, iv, r.y) + b.y;
    v.z = fmaf(a.z, iv, r.z) + b.z;
    v.w = fmaf(a.w, iv, r.w) + b.w;
    if (RELU) {
        v.x = fmaxf(v.x, 0.f); v.y = fmaxf(v.y, 0.f);
        v.z = fmaxf(v.z, 0.f); v.w = fmaxf(v.w, 0.f);
    }
    reinterpret_cast<float4*>(out)[(size_t)node * CH + c] = v;
}

__global__ void combine9_kernel(const float* __restrict__ agg, const float* __restrict__ ylr,
                                const float* __restrict__ bias, const float* __restrict__ inv,
                                float* __restrict__ out, int n) {
    int idx = blockIdx.x * blockDim.x + threadIdx.x;
    if (idx >= n * 9) return;
    int node = idx / 9, j = idx % 9;
    float iv = __ldg(inv + node);
    float v = fmaf(agg[(size_t)node * 9 + j], iv, ylr[(size_t)node * 18 + 9 + j]) + __ldg(bias + j);
    out[(size_t)node * 9 + j] = v;
}

// ---------------------------------------------------------------------------
// launch
// ---------------------------------------------------------------------------
extern "C" void kernel_launch(void* const* d_in, const int* in_sizes, int n_in,
                              void* d_out, int out_size) {
    const float* emb = (const float*)d_in[0];
    const int* ei = (const int*)d_in[1];
    // d_in[2] = edge_attr, unused by SAGEConv
    const float* wl0 = (const float*)d_in[3];
    const float* wr0 = (const float*)d_in[4];
    const float* b0  = (const float*)d_in[5];
    const float* wl1 = (const float*)d_in[6];
    const float* wr1 = (const float*)d_in[7];
    const float* b1  = (const float*)d_in[8];
    const float* wl2 = (const float*)d_in[9];
    const float* wr2 = (const float*)d_in[10];
    const float* b2  = (const float*)d_in[11];
    const float* wl3 = (const float*)d_in[12];
    const float* wr3 = (const float*)d_in[13];
    const float* b3  = (const float*)d_in[14];
    float* out = (float*)d_out;

    const int n = in_sizes[0] / 128;
    const int E = in_sizes[1] / 2;
    const int* src = ei;
    const int* dst = ei + E;

    float *ylr, *agg, *xbuf, *inv, *deg;
    cudaGetSymbolAddress((void**)&ylr, g_ylr);
    cudaGetSymbolAddress((void**)&agg, g_agg);
    cudaGetSymbolAddress((void**)&xbuf, g_x);
    cudaGetSymbolAddress((void**)&inv, g_inv);
    cudaGetSymbolAddress((void**)&deg, g_deg);

    // dynamic smem sizes
    const int SMEM0 = (128 * 128 + 128 * (128 + 4)) * 4;  // 133 KB
    const int SMEM1 = (64 * 64 + 128 * (64 + 4)) * 4;     // ~51 KB
    const int SMEM2 = (32 * 32 + 128 * (32 + 4)) * 4;     // ~22 KB
    cudaFuncSetAttribute((const void*)proj_kernel<128, 128, 128, 8, 8>,
                         cudaFuncAttributeMaxDynamicSharedMemorySize, SMEM0);
    cudaFuncSetAttribute((const void*)proj_kernel<64, 64, 128, 8, 4>,
                         cudaFuncAttributeMaxDynamicSharedMemorySize, SMEM1);

    const int TB = 256;
    auto cdiv = [](int a, int b) { return (a + b - 1) / b; };

    // degree
    zero_kernel<<<256, TB>>>(deg, n);
    deg_kernel<<<cdiv(E, TB), TB>>>(dst, deg, E);
    inv_kernel<<<cdiv(n, TB), TB>>>(deg, inv, n);

    // ---- layer 0: 128 -> 64, relu ----
    proj_kernel<128, 128, 128, 8, 8><<<cdiv(n, 128), 256, SMEM0>>>(emb, wl0, wr0, ylr, n);
    zero_kernel<<<512, TB>>>(agg, n * 64);
    scatter_kernel<64><<<cdiv(E * 16, TB), TB>>>(ylr, src, dst, agg, E);
    combine_kernel<64, true><<<cdiv(n * 16, TB), TB>>>(agg, ylr, b0, inv, xbuf, n);

    // ---- layer 1: 64 -> 32, relu ----
    proj_kernel<64, 64, 128, 8, 4><<<cdiv(n, 128), 256, SMEM1>>>(xbuf, wl1, wr1, ylr, n);
    zero_kernel<<<512, TB>>>(agg, n * 32);
    scatter_kernel<32><<<cdiv(E * 8, TB), TB>>>(ylr, src, dst, agg, E);
    combine_kernel<32, true><<<cdiv(n * 8, TB), TB>>>(agg, ylr, b1, inv, xbuf, n);

    // ---- layer 2: 32 -> 16, relu ----
    proj_kernel<32, 32, 128, 8, 2><<<cdiv(n, 128), 256, SMEM2>>>(xbuf, wl2, wr2, ylr, n);
    zero_kernel<<<512, TB>>>(agg, n * 16);
    scatter_kernel<16><<<cdiv(E * 4, TB), TB>>>(ylr, src, dst, agg, E);
    combine_kernel<16, true><<<cdiv(n * 4, TB), TB>>>(agg, ylr, b2, inv, xbuf, n);

    // ---- layer 3: 16 -> 9, no relu, write d_out ----
    proj3_kernel<<<cdiv(n, 128), 128>>>(xbuf, wl3, wr3, ylr, n);
    zero_kernel<<<512, TB>>>(agg, n * 9);
    scatter9_kernel<<<cdiv(E * 9, TB), TB>>>(ylr, src, dst, agg, E);
    combine9_kernel<<<cdiv(n * 9, TB), TB>>>(agg, ylr, b3, inv, out, n);
}

// round 2
// speedup vs baseline: 1.2721x; 1.2721x over previous
#include <cuda_runtime.h>
#include <cuda_bf16.h>
#include <cstdint>

#define NMAX 100000

// Scratch (static device globals — allocation-free per harness rules)
__device__ __align__(16) float g_ylr[NMAX * 128];  // projected [y_l | y_r], node-major
__device__ __align__(16) float g_agg[NMAX * 64];   // aggregation accumulator
__device__ __align__(16) float g_x[NMAX * 64];     // layer activations
__device__ __align__(16) float g_inv[NMAX];        // 1/max(deg,1)
__device__ __align__(16) float g_deg[NMAX];        // in-degree (float count)

// ---------------------------------------------------------------------------
// cp.async helpers
// ---------------------------------------------------------------------------
__device__ __forceinline__ void cp_async16(uint32_t dst, const void* src, int src_bytes) {
    asm volatile("cp.async.cg.shared.global [%0], [%1], 16, %2;\n"
                 :: "r"(dst), "l"(src), "r"(src_bytes));
}
__device__ __forceinline__ void cp_commit() { asm volatile("cp.async.commit_group;\n"); }
template <int N>
__device__ __forceinline__ void cp_wait() { asm volatile("cp.async.wait_group %0;\n" :: "n"(N)); }

// ---------------------------------------------------------------------------
// zero
// ---------------------------------------------------------------------------
__global__ void zero_kernel(float* __restrict__ p, int count) {
    int i = blockIdx.x * blockDim.x + threadIdx.x;
    int n4 = count >> 2;
    float4* p4 = reinterpret_cast<float4*>(p);
    float4 z = make_float4(0.f, 0.f, 0.f, 0.f);
    for (int j = i; j < n4; j += gridDim.x * blockDim.x) p4[j] = z;
    if (i == 0) {
        for (int j = n4 * 4; j < count; ++j) p[j] = 0.f;
    }
}

// ---------------------------------------------------------------------------
// degree
// ---------------------------------------------------------------------------
__global__ void deg_kernel(const int* __restrict__ dst, float* __restrict__ deg, int E) {
    int i = blockIdx.x * blockDim.x + threadIdx.x;
    if (i < E) atomicAdd(&deg[dst[i]], 1.0f);
}

__global__ void inv_kernel(const float* __restrict__ deg, float* __restrict__ inv, int n) {
    int i = blockIdx.x * blockDim.x + threadIdx.x;
    if (i < n) inv[i] = 1.0f / fmaxf(deg[i], 1.0f);
}

// ---------------------------------------------------------------------------
// projection GEMM: ylr[n x NC] = x[n x K] @ [wl | wr]  (NC = 2F combined)
// BK-tiled, cp.async double-buffered. TM=8 rows/thread, 8 cols/thread
// (two float4 groups split at ±NC/2 => conflict-free LDS.128 on B).
// ---------------------------------------------------------------------------
template <int K, int NC, int BM, int BK>
__global__ void __launch_bounds__((BM / 8) * (NC / 8), 2)
sgemm_proj(const float* __restrict__ x, const float* __restrict__ wl,
           const float* __restrict__ wr, float* __restrict__ ylr, int n) {
    constexpr int TM = 8;
    constexpr int PAD = 4;
    constexpr int F = NC / 2;
    constexpr int NTH = (BM / TM) * (NC / 8);
    constexpr int KT = K / BK;
    constexpr int XS = BK + PAD;

    __shared__ float sX[2][BM * XS];
    __shared__ float sB[2][BK * NC];

    const int tid = threadIdx.x;
    const int nb = blockIdx.x * BM;
    const int mrem = n - nb;

    auto load_tile = [&](int kb, int buf) {
        const int k0 = kb * BK;
        // X tile: BM x BK
        for (int idx = tid; idx < BM * BK / 4; idx += NTH) {
            int m = idx / (BK / 4);
            int kc = idx % (BK / 4);
            uint32_t dst = (uint32_t)__cvta_generic_to_shared(&sX[buf][m * XS + kc * 4]);
            int mm = (m < mrem) ? m : 0;
            const float* src = x + (size_t)(nb + mm) * K + k0 + kc * 4;
            cp_async16(dst, src, (m < mrem) ? 16 : 0);
        }
        // W tile: BK x NC  (cols [0,F) from wl, [F,NC) from wr)
        for (int idx = tid; idx < BK * NC / 4; idx += NTH) {
            int kr = idx / (NC / 4);
            int j = (idx % (NC / 4)) * 4;
            const float* src = (j < F) ? (wl + (size_t)(k0 + kr) * F + j)
                                       : (wr + (size_t)(k0 + kr) * F + (j - F));
            uint32_t dst = (uint32_t)__cvta_generic_to_shared(&sB[buf][kr * NC + j]);
            cp_async16(dst, src, 16);
        }
    };

    load_tile(0, 0);
    cp_commit();

    constexpr int CG = NC / 8;
    const int tj = tid % CG;
    const int ti = tid / CG;
    const int m0 = ti * TM;
    const int jA = tj * 4;
    const int jB = jA + F;

    float acc[TM][8];
#pragma unroll
    for (int i = 0; i < TM; ++i)
#pragma unroll
        for (int t = 0; t < 8; ++t) acc[i][t] = 0.f;

    for (int kb = 0; kb < KT; ++kb) {
        if (kb + 1 < KT) {
            load_tile(kb + 1, (kb + 1) & 1);
            cp_commit();
            cp_wait<1>();
        } else {
            cp_wait<0>();
        }
        __syncthreads();

        const float* bx = sX[kb & 1];
        const float* bb = sB[kb & 1];
#pragma unroll
        for (int k = 0; k < BK; ++k) {
            float4 b0 = *reinterpret_cast<const float4*>(&bb[k * NC + jA]);
            float4 b1 = *reinterpret_cast<const float4*>(&bb[k * NC + jB]);
#pragma unroll
            for (int i = 0; i < TM; ++i) {
                float a = bx[(m0 + i) * XS + k];
                acc[i][0] = fmaf(a, b0.x, acc[i][0]);
                acc[i][1] = fmaf(a, b0.y, acc[i][1]);
                acc[i][2] = fmaf(a, b0.z, acc[i][2]);
                acc[i][3] = fmaf(a, b0.w, acc[i][3]);
                acc[i][4] = fmaf(a, b1.x, acc[i][4]);
                acc[i][5] = fmaf(a, b1.y, acc[i][5]);
                acc[i][6] = fmaf(a, b1.z, acc[i][6]);
                acc[i][7] = fmaf(a, b1.w, acc[i][7]);
            }
        }
        __syncthreads();
    }

#pragma unroll
    for (int i = 0; i < TM; ++i) {
        int node = nb + m0 + i;
        if (node < n) {
            float4 v0 = make_float4(acc[i][0], acc[i][1], acc[i][2], acc[i][3]);
            float4 v1 = make_float4(acc[i][4], acc[i][5], acc[i][6], acc[i][7]);
            *reinterpret_cast<float4*>(&ylr[(size_t)node * NC + jA]) = v0;
            *reinterpret_cast<float4*>(&ylr[(size_t)node * NC + jB]) = v1;
        }
    }
}

// ---------------------------------------------------------------------------
// layer 3 projection (Fin=16, Fout=9): per-node kernel, stride 18
// ---------------------------------------------------------------------------
__global__ void proj3_kernel(const float* __restrict__ x, const float* __restrict__ wl,
                             const float* __restrict__ wr, float* __restrict__ ylr, int n) {
    __shared__ float swl[16 * 9];
    __shared__ float swr[16 * 9];
    for (int i = threadIdx.x; i < 144; i += blockDim.x) {
        swl[i] = wl[i];
        swr[i] = wr[i];
    }
    __syncthreads();

    int node = blockIdx.x * blockDim.x + threadIdx.x;
    if (node >= n) return;

    float xv[16];
    const float4* xr = reinterpret_cast<const float4*>(x + (size_t)node * 16);
#pragma unroll
    for (int c = 0; c < 4; ++c) {
        float4 v = xr[c];
        xv[c * 4 + 0] = v.x; xv[c * 4 + 1] = v.y; xv[c * 4 + 2] = v.z; xv[c * 4 + 3] = v.w;
    }
#pragma unroll
    for (int j = 0; j < 9; ++j) {
        float al = 0.f, ar = 0.f;
#pragma unroll
        for (int k = 0; k < 16; ++k) {
            al = fmaf(xv[k], swl[k * 9 + j], al);
            ar = fmaf(xv[k], swr[k * 9 + j], ar);
        }
        ylr[(size_t)node * 18 + j] = al;
        ylr[(size_t)node * 18 + 9 + j] = ar;
    }
}

// ---------------------------------------------------------------------------
// scatter: agg[dst] += y_l[src]   (vec4 reduction, F % 4 == 0)
// ---------------------------------------------------------------------------
template <int F>
__global__ void scatter_kernel(const float* __restrict__ ylr, const int* __restrict__ src,
                               const int* __restrict__ dst, float* __restrict__ agg, int E) {
    constexpr int CH = F / 4;
    int idx = blockIdx.x * blockDim.x + threadIdx.x;
    if (idx >= E * CH) return;
    int e = idx / CH, c = idx % CH;
    int s = __ldg(src + e), d = __ldg(dst + e);
    float4 v = reinterpret_cast<const float4*>(ylr)[(size_t)s * (2 * F / 4) + c];
    float* addr = agg + (size_t)d * F + c * 4;
    asm volatile("red.global.add.v4.f32 [%0], {%1, %2, %3, %4};"
                 :: "l"(addr), "f"(v.x), "f"(v.y), "f"(v.z), "f"(v.w)
                 : "memory");
}

__global__ void scatter9_kernel(const float* __restrict__ ylr, const int* __restrict__ src,
                                const int* __restrict__ dst, float* __restrict__ agg, int E) {
    int idx = blockIdx.x * blockDim.x + threadIdx.x;
    if (idx >= E * 9) return;
    int e = idx / 9, c = idx % 9;
    int s = __ldg(src + e), d = __ldg(dst + e);
    atomicAdd(agg + (size_t)d * 9 + c, ylr[(size_t)s * 18 + c]);
}

// ---------------------------------------------------------------------------
// combine: out = [relu]( agg/deg + y_r + b )
// ---------------------------------------------------------------------------
template <int F, bool RELU>
__global__ void combine_kernel(const float* __restrict__ agg, const float* __restrict__ ylr,
                               const float* __restrict__ bias, const float* __restrict__ inv,
                               float* __restrict__ out, int n) {
    constexpr int CH = F / 4;
    int idx = blockIdx.x * blockDim.x + threadIdx.x;
    if (idx >= n * CH) return;
    int node = idx / CH, c = idx % CH;
    float iv = __ldg(inv + node);
    float4 a = reinterpret_cast<const float4*>(agg)[(size_t)node * CH + c];
    float4 r = reinterpret_cast<const float4*>(ylr)[(size_t)node * (2 * CH) + CH + c];
    float4 b = reinterpret_cast<const float4*>(bias)[c];
    float4 v;
    v.x = fmaf(a.x, iv, r.x) + b.x;
    v.y = fmaf(a.y, iv, r.y) + b.y;
    v.z = fmaf(a.z, iv, r.z) + b.z;
    v.w = fmaf(a.w, iv, r.w) + b.w;
    if (RELU) {
        v.x = fmaxf(v.x, 0.f); v.y = fmaxf(v.y, 0.f);
        v.z = fmaxf(v.z, 0.f); v.w = fmaxf(v.w, 0.f);
    }
    reinterpret_cast<float4*>(out)[(size_t)node * CH + c] = v;
}

__global__ void combine9_kernel(const float* __restrict__ agg, const float* __restrict__ ylr,
                                const float* __restrict__ bias, const float* __restrict__ inv,
                                float* __restrict__ out, int n) {
    int idx = blockIdx.x * blockDim.x + threadIdx.x;
    if (idx >= n * 9) return;
    int node = idx / 9, j = idx % 9;
    float iv = __ldg(inv + node);
    float v = fmaf(agg[(size_t)node * 9 + j], iv, ylr[(size_t)node * 18 + 9 + j]) + __ldg(bias + j);
    out[(size_t)node * 9 + j] = v;
}

// ---------------------------------------------------------------------------
// launch
// ---------------------------------------------------------------------------
extern "C" void kernel_launch(void* const* d_in, const int* in_sizes, int n_in,
                              void* d_out, int out_size) {
    const float* emb = (const float*)d_in[0];
    const int* ei = (const int*)d_in[1];
    // d_in[2] = edge_attr, unused by SAGEConv
    const float* wl0 = (const float*)d_in[3];
    const float* wr0 = (const float*)d_in[4];
    const float* b0  = (const float*)d_in[5];
    const float* wl1 = (const float*)d_in[6];
    const float* wr1 = (const float*)d_in[7];
    const float* b1  = (const float*)d_in[8];
    const float* wl2 = (const float*)d_in[9];
    const float* wr2 = (const float*)d_in[10];
    const float* b2  = (const float*)d_in[11];
    const float* wl3 = (const float*)d_in[12];
    const float* wr3 = (const float*)d_in[13];
    const float* b3  = (const float*)d_in[14];
    float* out = (float*)d_out;

    const int n = in_sizes[0] / 128;
    const int E = in_sizes[1] / 2;
    const int* src = ei;
    const int* dst = ei + E;

    float *ylr, *agg, *xbuf, *inv, *deg;
    cudaGetSymbolAddress((void**)&ylr, g_ylr);
    cudaGetSymbolAddress((void**)&agg, g_agg);
    cudaGetSymbolAddress((void**)&xbuf, g_x);
    cudaGetSymbolAddress((void**)&inv, g_inv);
    cudaGetSymbolAddress((void**)&deg, g_deg);

    const int TB = 256;
    auto cdiv = [](int a, int b) { return (a + b - 1) / b; };

    // degree
    zero_kernel<<<256, TB>>>(deg, n);
    deg_kernel<<<cdiv(E, TB), TB>>>(dst, deg, E);
    inv_kernel<<<cdiv(n, TB), TB>>>(deg, inv, n);

    // ---- layer 0: 128 -> 64, relu ----
    sgemm_proj<128, 128, 128, 16><<<cdiv(n, 128), 256>>>(emb, wl0, wr0, ylr, n);
    zero_kernel<<<512, TB>>>(agg, n * 64);
    scatter_kernel<64><<<cdiv(E * 16, TB), TB>>>(ylr, src, dst, agg, E);
    combine_kernel<64, true><<<cdiv(n * 16, TB), TB>>>(agg, ylr, b0, inv, xbuf, n);

    // ---- layer 1: 64 -> 32, relu ----
    sgemm_proj<64, 64, 128, 16><<<cdiv(n, 128), 128>>>(xbuf, wl1, wr1, ylr, n);
    zero_kernel<<<512, TB>>>(agg, n * 32);
    scatter_kernel<32><<<cdiv(E * 8, TB), TB>>>(ylr, src, dst, agg, E);
    combine_kernel<32, true><<<cdiv(n * 8, TB), TB>>>(agg, ylr, b1, inv, xbuf, n);

    // ---- layer 2: 32 -> 16, relu ----
    sgemm_proj<32, 32, 128, 16><<<cdiv(n, 128), 64>>>(xbuf, wl2, wr2, ylr, n);
    zero_kernel<<<512, TB>>>(agg, n * 16);
    scatter_kernel<16><<<cdiv(E * 4, TB), TB>>>(ylr, src, dst, agg, E);
    combine_kernel<16, true><<<cdiv(n * 4, TB), TB>>>(agg, ylr, b2, inv, xbuf, n);

    // ---- layer 3: 16 -> 9, no relu, write d_out ----
    proj3_kernel<<<cdiv(n, 128), 128>>>(xbuf, wl3, wr3, ylr, n);
    zero_kernel<<<512, TB>>>(agg, n * 9);
    scatter9_kernel<<<cdiv(E * 9, TB), TB>>>(ylr, src, dst, agg, E);
    combine9_kernel<<<cdiv(n * 9, TB), TB>>>(agg, ylr, b3, inv, out, n);
}